// round 3
// baseline (speedup 1.0000x reference)
#include <cuda_runtime.h>
#include <cstdint>

// ---------------- problem constants ----------------
#define B_   8
#define S_   4096
#define D_   2048
#define M_   (B_*S_)        // 32768 tokens
#define E1_  (3*D_)         // 6144
#define NCHUNK 32
#define CHUNKS_S (S_/NCHUNK)

// ---------------- scratch (device globals) ----------------
__device__ float g_Q [67108864];
__device__ float g_K [67108864];
__device__ float g_V [67108864];
__device__ float g_Yb[67108864];
__device__ float g_Apart[(size_t)B_ * NCHUNK * D_];
__device__ float g_A[B_ * D_];

#define NEG_L2T_OVER_512 (-0.025952563241307517)

// ---------------- PTX helpers ----------------
__device__ __forceinline__ unsigned f2tf32(float x) {
    unsigned r;
    asm("cvt.rna.tf32.f32 %0, %1;" : "=r"(r) : "f"(x));
    return r;
}

__device__ __forceinline__ void mma_tf32(float c[4], unsigned a0, unsigned a1,
                                         unsigned a2, unsigned a3,
                                         unsigned b0, unsigned b1) {
    asm volatile(
        "mma.sync.aligned.m16n8k8.row.col.f32.tf32.tf32.f32 "
        "{%0,%1,%2,%3},{%4,%5,%6,%7},{%8,%9},{%0,%1,%2,%3};"
        : "+f"(c[0]), "+f"(c[1]), "+f"(c[2]), "+f"(c[3])
        : "r"(a0), "r"(a1), "r"(a2), "r"(a3), "r"(b0), "r"(b1));
}

// ---------------- TF32 GEMM: C[M,N] = A[M,K] * B[N,K]^T (+ epilogue) --------
// CTA tile 128x128, BK=16, 256 threads (8 warps: 4 in M x 2 in N).
// smem rows: 0..127 = A tile rows, 128..255 = B tile rows.
// Each smem row holds BK=16 tf32 values permuted: value with k-index k sits at
// position (k&3)*4 + (k>>2), so a thread's frag k-set {t, t+4, t+8, t+12} is
// one contiguous float4 at position t*4. Row stride LDSR=20 words (80B).
// MODE 0: A = X, outputs routed to g_Q/g_K/g_V by column section, bias=b_in.
// MODE 1: A = g_Yb, out = d_out, epilogue adds b_out + X residual.
#define BM 128
#define BN 128
#define BK 16
#define LDSR 20
#define STGW (256*LDSR)         // words per stage (A+B)
#define KT (D_/BK)              // 128 k-iterations

template <int MODE>
__global__ __launch_bounds__(256, 2)
void gemm_tf32(const float* __restrict__ Aparam,
               const float* __restrict__ Bg,
               const float* __restrict__ bias,
               const float* __restrict__ Xres,
               float* __restrict__ outParam)
{
    __shared__ unsigned sm[2][STGW];

    const float* __restrict__ Ag = (MODE == 0) ? Aparam : g_Yb;

    const int tid  = threadIdx.x;
    const int lane = tid & 31;
    const int warp = tid >> 5;
    const int wm   = (warp >> 1) * 32;   // warp M offset (4 warps in M)
    const int wn   = (warp & 1) * 64;    // warp N offset (2 warps in N)
    const int gID  = lane >> 2;          // 0..7
    const int tig  = lane & 3;           // 0..3

    const int    blockN = blockIdx.x * BN;
    const size_t blockM = (size_t)blockIdx.y * BM;

    // ---- staging plan: 4 x 16B chunks per thread (2 A + 2 B) ----
    const float* gsrc[4];
    int sbase[4];
    #pragma unroll
    for (int i = 0; i < 4; i++) {
        const int cid = i * 256 + tid;          // 0..1023
        if (i < 2) {
            const int row = cid >> 2;           // 0..127
            const int j   = cid & 3;
            gsrc[i]  = Ag + (blockM + row) * D_ + j * 4;
            sbase[i] = row * LDSR + j;
        } else {
            const int cid2 = cid - 512;
            const int row  = cid2 >> 2;         // 0..127
            const int j    = cid2 & 3;
            gsrc[i]  = Bg + ((size_t)blockN + row) * D_ + j * 4;
            sbase[i] = (128 + row) * LDSR + j;
        }
    }

    // frag LDS offsets (in words), computed once
    int aoff[2][2], boff[8];
    #pragma unroll
    for (int mi = 0; mi < 2; mi++)
        #pragma unroll
        for (int h = 0; h < 2; h++)
            aoff[mi][h] = (wm + mi * 16 + h * 8 + gID) * LDSR + tig * 4;
    #pragma unroll
    for (int ni = 0; ni < 8; ni++)
        boff[ni] = (128 + wn + ni * 8 + gID) * LDSR + tig * 4;

    float c[2][8][4];
    #pragma unroll
    for (int i = 0; i < 2; i++)
        #pragma unroll
        for (int j = 0; j < 8; j++)
            #pragma unroll
            for (int k = 0; k < 4; k++) c[i][j][k] = 0.f;

    // prologue: global prefetch of ktile 0
    float4 r[4];
    #pragma unroll
    for (int i = 0; i < 4; i++) r[i] = __ldg((const float4*)gsrc[i]);

    int buf = 0;
    for (int kt = 0; kt < KT; ++kt) {
        unsigned* s = sm[buf];
        // STS with rna-tf32 conversion + k-permutation scatter
        #pragma unroll
        for (int i = 0; i < 4; i++) {
            s[sbase[i]]      = f2tf32(r[i].x);
            s[sbase[i] + 4]  = f2tf32(r[i].y);
            s[sbase[i] + 8]  = f2tf32(r[i].z);
            s[sbase[i] + 12] = f2tf32(r[i].w);
        }
        // prefetch next ktile
        if (kt + 1 < KT) {
            #pragma unroll
            for (int i = 0; i < 4; i++)
                r[i] = __ldg((const float4*)(gsrc[i] + (size_t)(kt + 1) * BK));
        }
        __syncthreads();

        // fragment loads: 4 A + 8 B vectorized LDS.128
        uint4 A4[2][2];
        #pragma unroll
        for (int mi = 0; mi < 2; mi++)
            #pragma unroll
            for (int h = 0; h < 2; h++)
                A4[mi][h] = *(const uint4*)&s[aoff[mi][h]];
        uint4 B4[8];
        #pragma unroll
        for (int ni = 0; ni < 8; ni++)
            B4[ni] = *(const uint4*)&s[boff[ni]];

        // ks = 0: k in {tig, tig+4}  (components .x, .y)
        #pragma unroll
        for (int ni = 0; ni < 8; ni++) {
            mma_tf32(c[0][ni], A4[0][0].x, A4[0][1].x, A4[0][0].y, A4[0][1].y,
                     B4[ni].x, B4[ni].y);
            mma_tf32(c[1][ni], A4[1][0].x, A4[1][1].x, A4[1][0].y, A4[1][1].y,
                     B4[ni].x, B4[ni].y);
        }
        // ks = 1: k in {tig+8, tig+12} (components .z, .w)
        #pragma unroll
        for (int ni = 0; ni < 8; ni++) {
            mma_tf32(c[0][ni], A4[0][0].z, A4[0][1].z, A4[0][0].w, A4[0][1].w,
                     B4[ni].z, B4[ni].w);
            mma_tf32(c[1][ni], A4[1][0].z, A4[1][1].z, A4[1][0].w, A4[1][1].w,
                     B4[ni].z, B4[ni].w);
        }
        buf ^= 1;
    }

    // ---------------- epilogue ----------------
    float* __restrict__ dst;
    int colBase;
    if (MODE == 0) {
        const int sect = blockN >> 11;          // 0:Q 1:K 2:V
        dst = (sect == 0) ? g_Q : ((sect == 1) ? g_K : g_V);
        colBase = blockN & (D_ - 1);
    } else {
        dst = outParam;
        colBase = blockN;
    }

    #pragma unroll
    for (int mi = 0; mi < 2; ++mi) {
        const size_t rA = blockM + wm + mi * 16 + gID;
        const size_t rB = rA + 8;
        #pragma unroll
        for (int ni = 0; ni < 8; ++ni) {
            const int e  = blockN + wn + ni * 8 + tig * 2;   // global bias col
            const int el = colBase + wn + ni * 8 + tig * 2;  // col in dst
            const float bv0 = __ldg(&bias[e]);
            const float bv1 = __ldg(&bias[e + 1]);
            float2 v0 = make_float2(c[mi][ni][0] + bv0, c[mi][ni][1] + bv1);
            float2 v1 = make_float2(c[mi][ni][2] + bv0, c[mi][ni][3] + bv1);
            if (MODE == 1) {
                const float2 x0 = *(const float2*)(Xres + rA * D_ + el);
                const float2 x1 = *(const float2*)(Xres + rB * D_ + el);
                v0.x += x0.x; v0.y += x0.y;
                v1.x += x1.x; v1.y += x1.y;
            }
            *(float2*)(dst + rA * D_ + el) = v0;
            *(float2*)(dst + rB * D_ + el) = v1;
        }
    }
}

// -------- reduction stage 1: per (batch, chunk) partial of fm(rope(K)) * V ---
__global__ __launch_bounds__(256)
void reduce_A_kernel()
{
    const int b     = blockIdx.x >> 5;
    const int chunk = blockIdx.x & 31;
    const int tid   = threadIdx.x;
    __shared__ float red[8];

    float acc[8];
    #pragma unroll
    for (int j = 0; j < 8; j++) acc[j] = 0.f;

    float invf[2];
    #pragma unroll
    for (int j = 0; j < 2; j++) {
        const int p = tid + 256 * j;
        invf[j] = exp2f((float)p * (float)NEG_L2T_OVER_512);
    }

    const int s0 = chunk * CHUNKS_S;
    for (int s = s0; s < s0 + CHUNKS_S; ++s) {
        const size_t rowoff = ((size_t)b * S_ + s) * D_;
        float kr[8];
        float sq = 0.f;
        #pragma unroll
        for (int j = 0; j < 4; ++j) {
            const int p = tid + 256 * j;
            const float2 kv = *(const float2*)(g_K + rowoff + 2 * p);
            float x0 = kv.x, x1 = kv.y;
            if (j < 2) {
                float sn, cs;
                sincosf((float)s * invf[j], &sn, &cs);
                const float r0 = x0 * cs - x1 * sn;
                const float r1 = x1 * cs + x0 * sn;
                x0 = r0; x1 = r1;
            }
            kr[2 * j] = x0; kr[2 * j + 1] = x1;
            sq = fmaf(x0, x0, fmaf(x1, x1, sq));
        }
        #pragma unroll
        for (int o = 16; o; o >>= 1) sq += __shfl_xor_sync(0xffffffffu, sq, o);
        if ((tid & 31) == 0) red[tid >> 5] = sq;
        __syncthreads();
        const float tot = red[0] + red[1] + red[2] + red[3]
                        + red[4] + red[5] + red[6] + red[7];
        __syncthreads();
        const float inv_n = 1.f / fmaxf(sqrtf(tot), 1e-12f);

        #pragma unroll
        for (int j = 0; j < 4; ++j) {
            const int p = tid + 256 * j;
            const float2 vv = *(const float2*)(g_V + rowoff + 2 * p);
            acc[2 * j]     = fmaf(kr[2 * j]     * inv_n, vv.x, acc[2 * j]);
            acc[2 * j + 1] = fmaf(kr[2 * j + 1] * inv_n, vv.y, acc[2 * j + 1]);
        }
    }
    float* dstp = g_Apart + ((size_t)b * NCHUNK + chunk) * D_;
    #pragma unroll
    for (int j = 0; j < 4; ++j) {
        const int p = tid + 256 * j;
        *(float2*)(dstp + 2 * p) = make_float2(acc[2 * j], acc[2 * j + 1]);
    }
}

// -------- reduction stage 2: fixed-order finalize ----------------------------
__global__ void finalize_A_kernel()
{
    const int i = blockIdx.x * 256 + threadIdx.x;   // i < B_*D_
    const int b = i >> 11;
    const int d = i & (D_ - 1);
    float s = 0.f;
    #pragma unroll
    for (int c = 0; c < NCHUNK; ++c)
        s += g_Apart[((size_t)b * NCHUNK + c) * D_ + d];
    g_A[i] = s;
}

// -------- Yb = A (broadcast over s) * rope(Q) --------------------------------
__global__ __launch_bounds__(256)
void yb_kernel()
{
    const int m = blockIdx.x;
    const int b = m >> 12;
    const int s = m & (S_ - 1);
    const int tid = threadIdx.x;
    const size_t rowoff = (size_t)m * D_;
    const float* Arow = g_A + b * D_;

    #pragma unroll
    for (int j = 0; j < 4; ++j) {
        const int p = tid + 256 * j;
        const float2 q = *(const float2*)(g_Q + rowoff + 2 * p);
        float x0 = q.x, x1 = q.y;
        if (j < 2) {
            const float invf = exp2f((float)p * (float)NEG_L2T_OVER_512);
            float sn, cs;
            sincosf((float)s * invf, &sn, &cs);
            const float r0 = x0 * cs - x1 * sn;
            const float r1 = x1 * cs + x0 * sn;
            x0 = r0; x1 = r1;
        }
        const float2 a = *(const float2*)(Arow + 2 * p);
        *(float2*)(g_Yb + rowoff + 2 * p) = make_float2(a.x * x0, a.y * x1);
    }
}

// ---------------- launch ------------------------------------------------------
extern "C" void kernel_launch(void* const* d_in, const int* in_sizes, int n_in,
                              void* d_out, int out_size)
{
    const float* X     = (const float*)d_in[0];   // [8,4096,2048]
    const float* W_in  = (const float*)d_in[1];   // [6144,2048]
    const float* b_in  = (const float*)d_in[2];   // [6144]
    const float* W_out = (const float*)d_in[3];   // [2048,2048]
    const float* b_out = (const float*)d_in[4];   // [2048]
    float* out = (float*)d_out;

    // 1) QKV = X @ W_in^T + b_in  ->  g_Q, g_K, g_V
    gemm_tf32<0><<<dim3(E1_ / BN, M_ / BM), 256>>>(X, W_in, b_in, nullptr, nullptr);

    // 2) A = sum_s fm(rope(K)) * V   (two-stage, deterministic)
    reduce_A_kernel<<<B_ * NCHUNK, 256>>>();
    finalize_A_kernel<<<(B_ * D_) / 256, 256>>>();

    // 3) Yb = A ⊙ rope(Q)
    yb_kernel<<<M_, 256>>>();

    // 4) out = Yb @ W_out^T + b_out + X
    gemm_tf32<1><<<dim3(D_ / BN, M_ / BM), 256>>>(nullptr, W_out, b_out, X, out);

    (void)in_sizes; (void)n_in; (void)out_size;
}

// round 4
// speedup vs baseline: 1.6164x; 1.6164x over previous
#include <cuda_runtime.h>
#include <cstdint>

// ---------------- problem constants ----------------
#define B_   8
#define S_   4096
#define D_   2048
#define M_   (B_*S_)        // 32768 tokens
#define E1_  (3*D_)         // 6144
#define NCHUNK 32
#define CHUNKS_S (S_/NCHUNK)

// ---------------- scratch (device globals) ----------------
__device__ float g_Q  [67108864];   // [M, D] fp32
__device__ float g_K  [67108864];
__device__ float g_V  [67108864];
__device__ float g_Yb [67108864];   // pre-rounded to tf32 grid
__device__ float g_Xc [67108864];   // rna(X)
__device__ float g_W1c[(size_t)E1_ * D_];   // rna(W_in)
__device__ float g_W2c[(size_t)D_ * D_];    // rna(W_out)
__device__ float g_Apart[(size_t)B_ * NCHUNK * D_];
__device__ float g_A[B_ * D_];

#define NEG_L2T_OVER_512 (-0.025952563241307517)

// ---------------- PTX helpers ----------------
__device__ __forceinline__ void cp_async16(void* sdst, const void* gsrc) {
    unsigned saddr = (unsigned)__cvta_generic_to_shared(sdst);
    asm volatile("cp.async.cg.shared.global [%0], [%1], 16;" :: "r"(saddr), "l"(gsrc));
}
#define CP_COMMIT() asm volatile("cp.async.commit_group;")
#define CP_WAIT1()  asm volatile("cp.async.wait_group 1;")

__device__ __forceinline__ unsigned f2tf32(float x) {
    unsigned r;
    asm("cvt.rna.tf32.f32 %0, %1;" : "=r"(r) : "f"(x));
    return r;
}

__device__ __forceinline__ void mma_tf32(float c[4], const unsigned a[4],
                                         unsigned b0, unsigned b1) {
    asm volatile(
        "mma.sync.aligned.m16n8k8.row.col.f32.tf32.tf32.f32 "
        "{%0,%1,%2,%3},{%4,%5,%6,%7},{%8,%9},{%0,%1,%2,%3};"
        : "+f"(c[0]), "+f"(c[1]), "+f"(c[2]), "+f"(c[3])
        : "r"(a[0]), "r"(a[1]), "r"(a[2]), "r"(a[3]), "r"(b0), "r"(b1));
}

// -------- pre-round a tensor to the tf32 grid (rna) --------------------------
__global__ __launch_bounds__(256)
void round_tf32_kernel(const float* __restrict__ src, float* __restrict__ dst,
                       int n4)   // element count / 4
{
    const int i = blockIdx.x * 256 + threadIdx.x;
    if (i >= n4) return;
    const float4 v = __ldg((const float4*)src + i);
    float4 o;
    o.x = __uint_as_float(f2tf32(v.x));
    o.y = __uint_as_float(f2tf32(v.y));
    o.z = __uint_as_float(f2tf32(v.z));
    o.w = __uint_as_float(f2tf32(v.w));
    ((float4*)dst)[i] = o;
}

// ---------------- TF32 GEMM: C[M,N] = A[M,K] * B[N,K]^T (+ epilogue) --------
// Operands are PRE-ROUNDED to the tf32 grid in global memory, so the inner
// loop feeds raw fp32 bits to the MMA (HW truncation is identity on them).
// MODE 0: A = g_Xc, outputs routed to g_Q/g_K/g_V by column section, bias=b_in.
// MODE 1: A = g_Yb (pre-rounded), out = d_out, epilogue adds b_out + X residual.
#define BM 128
#define BN 128
#define BK 16
#define LDSR 20                 // BK + 4 pad floats
#define KT (D_/BK)              // 128 k-iterations

template <int MODE>
__global__ __launch_bounds__(256, 2)
void gemm_tf32(const float* __restrict__ Bg,
               const float* __restrict__ bias,
               const float* __restrict__ Xres,
               float* __restrict__ outParam)
{
    __shared__ float As[2][BM * LDSR];
    __shared__ float Bs[2][BN * LDSR];

    const float* __restrict__ Ag = (MODE == 0) ? g_Xc : g_Yb;

    const int tid  = threadIdx.x;
    const int lane = tid & 31;
    const int warp = tid >> 5;
    const int wm   = (warp >> 1) * 32;   // 4 warps in M
    const int wn   = (warp & 1) * 64;    // 2 warps in N
    const int gID  = lane >> 2;          // 0..7
    const int tig  = lane & 3;           // 0..3

    const int    blockN = blockIdx.x * BN;
    const size_t blockM = (size_t)blockIdx.y * BM;

    const int ldRow = tid >> 2;          // 0..63
    const int ldCol = (tid & 3) * 4;     // float offset (16B chunks)

    float c[2][8][4];
    #pragma unroll
    for (int i = 0; i < 2; i++)
        #pragma unroll
        for (int j = 0; j < 8; j++)
            #pragma unroll
            for (int k = 0; k < 4; k++) c[i][j][k] = 0.f;

    // prologue: load tile 0 into buffer 0
    {
        #pragma unroll
        for (int i = 0; i < 2; i++) {
            const int row = ldRow + i * 64;
            cp_async16(&As[0][row * LDSR + ldCol],
                       Ag + (blockM + row) * D_ + ldCol);
            cp_async16(&Bs[0][row * LDSR + ldCol],
                       Bg + ((size_t)blockN + row) * D_ + ldCol);
        }
    }
    CP_COMMIT();

    int buf = 0;
    for (int kt = 0; kt < KT; ++kt) {
        if (kt + 1 < KT) {
            const int k0 = (kt + 1) * BK;
            const int nb = buf ^ 1;
            #pragma unroll
            for (int i = 0; i < 2; i++) {
                const int row = ldRow + i * 64;
                cp_async16(&As[nb][row * LDSR + ldCol],
                           Ag + (blockM + row) * D_ + k0 + ldCol);
                cp_async16(&Bs[nb][row * LDSR + ldCol],
                           Bg + ((size_t)blockN + row) * D_ + k0 + ldCol);
            }
        }
        CP_COMMIT();
        CP_WAIT1();
        __syncthreads();

        #pragma unroll
        for (int ks = 0; ks < 2; ++ks) {
            const int kk = ks * 8;
            unsigned a[2][4];
            #pragma unroll
            for (int mi = 0; mi < 2; ++mi) {
                const float* ap = &As[buf][(wm + mi * 16 + gID) * LDSR + kk + tig];
                a[mi][0] = __float_as_uint(ap[0]);
                a[mi][1] = __float_as_uint(ap[8 * LDSR]);
                a[mi][2] = __float_as_uint(ap[4]);
                a[mi][3] = __float_as_uint(ap[8 * LDSR + 4]);
            }
            #pragma unroll
            for (int ni = 0; ni < 8; ++ni) {
                const float* bp = &Bs[buf][(wn + ni * 8 + gID) * LDSR + kk + tig];
                const unsigned b0 = __float_as_uint(bp[0]);
                const unsigned b1 = __float_as_uint(bp[4]);
                mma_tf32(c[0][ni], a[0], b0, b1);
                mma_tf32(c[1][ni], a[1], b0, b1);
            }
        }
        __syncthreads();
        buf ^= 1;
    }

    // ---------------- epilogue ----------------
    float* __restrict__ dst;
    int colBase;
    if (MODE == 0) {
        const int sect = blockN >> 11;          // 0:Q 1:K 2:V
        dst = (sect == 0) ? g_Q : ((sect == 1) ? g_K : g_V);
        colBase = blockN & (D_ - 1);
    } else {
        dst = outParam;
        colBase = blockN;
    }

    #pragma unroll
    for (int mi = 0; mi < 2; ++mi) {
        const size_t rA = blockM + wm + mi * 16 + gID;
        const size_t rB = rA + 8;
        #pragma unroll
        for (int ni = 0; ni < 8; ++ni) {
            const int e  = blockN + wn + ni * 8 + tig * 2;
            const int el = colBase + wn + ni * 8 + tig * 2;
            const float bv0 = __ldg(&bias[e]);
            const float bv1 = __ldg(&bias[e + 1]);
            float2 v0 = make_float2(c[mi][ni][0] + bv0, c[mi][ni][1] + bv1);
            float2 v1 = make_float2(c[mi][ni][2] + bv0, c[mi][ni][3] + bv1);
            if (MODE == 1) {
                const float2 x0 = *(const float2*)(Xres + rA * D_ + el);
                const float2 x1 = *(const float2*)(Xres + rB * D_ + el);
                v0.x += x0.x; v0.y += x0.y;
                v1.x += x1.x; v1.y += x1.y;
            }
            *(float2*)(dst + rA * D_ + el) = v0;
            *(float2*)(dst + rB * D_ + el) = v1;
        }
    }
}

// -------- reduction stage 1: per (batch, chunk) partial of fm(rope(K)) * V ---
__global__ __launch_bounds__(256)
void reduce_A_kernel()
{
    const int b     = blockIdx.x >> 5;
    const int chunk = blockIdx.x & 31;
    const int tid   = threadIdx.x;
    __shared__ float red[8];

    float acc[8];
    #pragma unroll
    for (int j = 0; j < 8; j++) acc[j] = 0.f;

    float invf[2];
    #pragma unroll
    for (int j = 0; j < 2; j++) {
        const int p = tid + 256 * j;
        invf[j] = exp2f((float)p * (float)NEG_L2T_OVER_512);
    }

    const int s0 = chunk * CHUNKS_S;
    for (int s = s0; s < s0 + CHUNKS_S; ++s) {
        const size_t rowoff = ((size_t)b * S_ + s) * D_;
        float kr[8];
        float sq = 0.f;
        #pragma unroll
        for (int j = 0; j < 4; ++j) {
            const int p = tid + 256 * j;
            const float2 kv = *(const float2*)(g_K + rowoff + 2 * p);
            float x0 = kv.x, x1 = kv.y;
            if (j < 2) {
                float sn, cs;
                sincosf((float)s * invf[j], &sn, &cs);
                const float r0 = x0 * cs - x1 * sn;
                const float r1 = x1 * cs + x0 * sn;
                x0 = r0; x1 = r1;
            }
            kr[2 * j] = x0; kr[2 * j + 1] = x1;
            sq = fmaf(x0, x0, fmaf(x1, x1, sq));
        }
        #pragma unroll
        for (int o = 16; o; o >>= 1) sq += __shfl_xor_sync(0xffffffffu, sq, o);
        if ((tid & 31) == 0) red[tid >> 5] = sq;
        __syncthreads();
        const float tot = red[0] + red[1] + red[2] + red[3]
                        + red[4] + red[5] + red[6] + red[7];
        __syncthreads();
        const float inv_n = 1.f / fmaxf(sqrtf(tot), 1e-12f);

        #pragma unroll
        for (int j = 0; j < 4; ++j) {
            const int p = tid + 256 * j;
            const float2 vv = *(const float2*)(g_V + rowoff + 2 * p);
            acc[2 * j]     = fmaf(kr[2 * j]     * inv_n, vv.x, acc[2 * j]);
            acc[2 * j + 1] = fmaf(kr[2 * j + 1] * inv_n, vv.y, acc[2 * j + 1]);
        }
    }
    float* dstp = g_Apart + ((size_t)b * NCHUNK + chunk) * D_;
    #pragma unroll
    for (int j = 0; j < 4; ++j) {
        const int p = tid + 256 * j;
        *(float2*)(dstp + 2 * p) = make_float2(acc[2 * j], acc[2 * j + 1]);
    }
}

// -------- reduction stage 2: fixed-order finalize ----------------------------
__global__ void finalize_A_kernel()
{
    const int i = blockIdx.x * 256 + threadIdx.x;
    const int b = i >> 11;
    const int d = i & (D_ - 1);
    float s = 0.f;
    #pragma unroll
    for (int c = 0; c < NCHUNK; ++c)
        s += g_Apart[((size_t)b * NCHUNK + c) * D_ + d];
    g_A[i] = s;
}

// -------- Yb = rna(A * rope(Q)) — pre-rounded for GEMM2 ----------------------
__global__ __launch_bounds__(256)
void yb_kernel()
{
    const int m = blockIdx.x;
    const int b = m >> 12;
    const int s = m & (S_ - 1);
    const int tid = threadIdx.x;
    const size_t rowoff = (size_t)m * D_;
    const float* Arow = g_A + b * D_;

    #pragma unroll
    for (int j = 0; j < 4; ++j) {
        const int p = tid + 256 * j;
        const float2 q = *(const float2*)(g_Q + rowoff + 2 * p);
        float x0 = q.x, x1 = q.y;
        if (j < 2) {
            const float invf = exp2f((float)p * (float)NEG_L2T_OVER_512);
            float sn, cs;
            sincosf((float)s * invf, &sn, &cs);
            const float r0 = x0 * cs - x1 * sn;
            const float r1 = x1 * cs + x0 * sn;
            x0 = r0; x1 = r1;
        }
        const float2 a = *(const float2*)(Arow + 2 * p);
        float2 o = make_float2(__uint_as_float(f2tf32(a.x * x0)),
                               __uint_as_float(f2tf32(a.y * x1)));
        *(float2*)(g_Yb + rowoff + 2 * p) = o;
    }
}

// ---------------- launch ------------------------------------------------------
extern "C" void kernel_launch(void* const* d_in, const int* in_sizes, int n_in,
                              void* d_out, int out_size)
{
    const float* X     = (const float*)d_in[0];   // [8,4096,2048]
    const float* W_in  = (const float*)d_in[1];   // [6144,2048]
    const float* b_in  = (const float*)d_in[2];   // [6144]
    const float* W_out = (const float*)d_in[3];   // [2048,2048]
    const float* b_out = (const float*)d_in[4];   // [2048]
    float* out = (float*)d_out;

    float* xc; float* w1c; float* w2c;
    cudaGetSymbolAddress((void**)&xc,  g_Xc);
    cudaGetSymbolAddress((void**)&w1c, g_W1c);
    cudaGetSymbolAddress((void**)&w2c, g_W2c);

    // 0) pre-round operands to the tf32 grid (bit-identical to in-loop cvt)
    round_tf32_kernel<<<(M_ * (D_/4) + 255) / 256, 256>>>(X, xc, M_ * (D_/4));
    round_tf32_kernel<<<((E1_ * (D_/4)) + 255) / 256, 256>>>(W_in, w1c, E1_ * (D_/4));
    round_tf32_kernel<<<((D_ * (D_/4)) + 255) / 256, 256>>>(W_out, w2c, D_ * (D_/4));

    // 1) QKV = X @ W_in^T + b_in  ->  g_Q, g_K, g_V
    gemm_tf32<0><<<dim3(E1_ / BN, M_ / BM), 256>>>(w1c, b_in, nullptr, nullptr);

    // 2) A = sum_s fm(rope(K)) * V
    reduce_A_kernel<<<B_ * NCHUNK, 256>>>();
    finalize_A_kernel<<<(B_ * D_) / 256, 256>>>();

    // 3) Yb = rna(A ⊙ rope(Q))
    yb_kernel<<<M_, 256>>>();

    // 4) out = Yb @ W_out^T + b_out + X
    gemm_tf32<1><<<dim3(D_ / BN, M_ / BM), 256>>>(w2c, b_out, X, out);

    (void)in_sizes; (void)n_in; (void)out_size;
}

// round 5
// speedup vs baseline: 1.8222x; 1.1273x over previous
#include <cuda_runtime.h>
#include <cstdint>

// ---------------- problem constants ----------------
#define B_   8
#define S_   4096
#define D_   2048
#define M_   (B_*S_)        // 32768 tokens
#define E1_  (3*D_)         // 6144
#define NCHUNK 128
#define CHUNKS_S (S_/NCHUNK)   // 32

// ---------------- scratch (device globals) ----------------
__device__ float g_Q  [67108864];   // [M, D] fp32 (natural layout)
__device__ float g_K  [67108864];
__device__ float g_V  [67108864];
__device__ float g_Yb [67108864];   // rna-rounded + k-permuted (GEMM2 A input)
__device__ float g_Xc [67108864];   // rna(X), k-permuted
__device__ float g_W1c[(size_t)E1_ * D_];   // rna(W_in), k-permuted
__device__ float g_W2c[(size_t)D_ * D_];    // rna(W_out), k-permuted
__device__ float g_Apart[(size_t)B_ * NCHUNK * D_];
__device__ float g_A[B_ * D_];

#define NEG_L2T_OVER_512 (-0.025952563241307517)

// ---------------- PTX helpers ----------------
__device__ __forceinline__ void cp_async16(void* sdst, const void* gsrc) {
    unsigned saddr = (unsigned)__cvta_generic_to_shared(sdst);
    asm volatile("cp.async.cg.shared.global [%0], [%1], 16;" :: "r"(saddr), "l"(gsrc));
}
#define CP_COMMIT() asm volatile("cp.async.commit_group;")
#define CP_WAIT1()  asm volatile("cp.async.wait_group 1;")

__device__ __forceinline__ unsigned f2tf32(float x) {
    unsigned r;
    asm("cvt.rna.tf32.f32 %0, %1;" : "=r"(r) : "f"(x));
    return r;
}

__device__ __forceinline__ void mma_tf32(float c[4], unsigned a0, unsigned a1,
                                         unsigned a2, unsigned a3,
                                         unsigned b0, unsigned b1) {
    asm volatile(
        "mma.sync.aligned.m16n8k8.row.col.f32.tf32.tf32.f32 "
        "{%0,%1,%2,%3},{%4,%5,%6,%7},{%8,%9},{%0,%1,%2,%3};"
        : "+f"(c[0]), "+f"(c[1]), "+f"(c[2]), "+f"(c[3])
        : "r"(a0), "r"(a1), "r"(a2), "r"(a3), "r"(b0), "r"(b1));
}

// -------- pre-round to tf32 grid + permute within each 16-col group ----------
// Permutation: element with k-index k sits at position perm(k)=(k&3)*4+(k>>2)
// (involution). Output 16B chunk j of group g holds src k = {j, j+4, j+8, j+12}.
__global__ __launch_bounds__(256)
void round_perm_kernel(const float* __restrict__ src, float* __restrict__ dst,
                       int n4)   // element count / 4
{
    const int c = blockIdx.x * 256 + threadIdx.x;
    if (c >= n4) return;
    const int g = c >> 2, j = c & 3;
    const float* s = src + (size_t)g * 16 + j;
    float4 o;
    o.x = __uint_as_float(f2tf32(s[0]));
    o.y = __uint_as_float(f2tf32(s[4]));
    o.z = __uint_as_float(f2tf32(s[8]));
    o.w = __uint_as_float(f2tf32(s[12]));
    ((float4*)dst)[c] = o;
}

// ---------------- TF32 GEMM: C[M,N] = A[M,K] * B[N,K]^T (+ epilogue) --------
// Inputs pre-rounded (tf32 grid) and k-permuted in global memory.
// cp.async 3-stage pipeline; LDS.128 fragment loads (conflict-free, LDSR=16).
// MODE 0: A=g_Xc, outputs routed to g_Q/g_K/g_V, bias=b_in.
// MODE 1: A=g_Yb, out=d_out, epilogue adds b_out + X residual.
#define BM 128
#define BN 128
#define BK 16
#define LDSR 16                 // words per row; stride ≡16 mod 32 banks
#define KT (D_/BK)              // 128 k-iterations
#define NSTG 3

template <int MODE>
__global__ __launch_bounds__(256, 2)
void gemm_tf32(const float* __restrict__ Bg,
               const float* __restrict__ bias,
               const float* __restrict__ Xres,
               float* __restrict__ outParam)
{
    __shared__ float As[NSTG][BM * LDSR];   // 24 KB
    __shared__ float Bs[NSTG][BN * LDSR];   // 24 KB  (total 48 KB)

    const float* __restrict__ Ag = (MODE == 0) ? g_Xc : g_Yb;

    const int tid  = threadIdx.x;
    const int lane = tid & 31;
    const int warp = tid >> 5;
    const int wm   = (warp >> 1) * 32;   // 4 warps in M
    const int wn   = (warp & 1) * 64;    // 2 warps in N
    const int gID  = lane >> 2;          // 0..7
    const int tig  = lane & 3;           // 0..3

    const int    blockN = blockIdx.x * BN;
    const size_t blockM = (size_t)blockIdx.y * BM;

    const int ldRow = tid >> 2;          // 0..63
    const int ldCol = (tid & 3) * 4;     // word offset of 16B chunk

    // fragment word offsets (16B aligned)
    int aoff[2][2], boff[8];
    #pragma unroll
    for (int mi = 0; mi < 2; mi++)
        #pragma unroll
        for (int h = 0; h < 2; h++)
            aoff[mi][h] = (wm + mi * 16 + h * 8 + gID) * LDSR + tig * 4;
    #pragma unroll
    for (int ni = 0; ni < 8; ni++)
        boff[ni] = (wn + ni * 8 + gID) * LDSR + tig * 4;

    float c[2][8][4];
    #pragma unroll
    for (int i = 0; i < 2; i++)
        #pragma unroll
        for (int j = 0; j < 8; j++)
            #pragma unroll
            for (int k = 0; k < 4; k++) c[i][j][k] = 0.f;

    // prologue: stage tiles 0 and 1 (one commit group each)
    #pragma unroll
    for (int stg = 0; stg < 2; ++stg) {
        const int k0 = stg * BK;
        #pragma unroll
        for (int i = 0; i < 2; i++) {
            const int row = ldRow + i * 64;
            cp_async16(&As[stg][row * LDSR + ldCol],
                       Ag + (blockM + row) * D_ + k0 + ldCol);
            cp_async16(&Bs[stg][row * LDSR + ldCol],
                       Bg + ((size_t)blockN + row) * D_ + k0 + ldCol);
        }
        CP_COMMIT();
    }

    int rd = 0, wr = 2;
    for (int kt = 0; kt < KT; ++kt) {
        // tile kt committed 2 iterations ago -> wait until <=1 group pending
        CP_WAIT1();
        __syncthreads();
        // Stage wr=(kt+2)%3 was read during compute kt-1; the barrier above is
        // after every thread's compute kt-1, so overwriting it now is safe.
        if (kt + 2 < KT) {
            const int k0 = (kt + 2) * BK;
            #pragma unroll
            for (int i = 0; i < 2; i++) {
                const int row = ldRow + i * 64;
                cp_async16(&As[wr][row * LDSR + ldCol],
                           Ag + (blockM + row) * D_ + k0 + ldCol);
                cp_async16(&Bs[wr][row * LDSR + ldCol],
                           Bg + ((size_t)blockN + row) * D_ + k0 + ldCol);
            }
        }
        CP_COMMIT();

        const float* sA = As[rd];
        const float* sB = Bs[rd];

        // A fragments: 4x LDS.128; each holds k = {tig, tig+4, tig+8, tig+12}
        uint4 A4[2][2];
        #pragma unroll
        for (int mi = 0; mi < 2; mi++)
            #pragma unroll
            for (int h = 0; h < 2; h++)
                A4[mi][h] = *(const uint4*)(sA + aoff[mi][h]);

        // B per-ni: 1x LDS.128 feeding 4 MMAs (ks0 uses .x/.y, ks1 uses .z/.w)
        #pragma unroll
        for (int ni = 0; ni < 8; ++ni) {
            const uint4 b = *(const uint4*)(sB + boff[ni]);
            mma_tf32(c[0][ni], A4[0][0].x, A4[0][1].x, A4[0][0].y, A4[0][1].y,
                     b.x, b.y);
            mma_tf32(c[1][ni], A4[1][0].x, A4[1][1].x, A4[1][0].y, A4[1][1].y,
                     b.x, b.y);
            mma_tf32(c[0][ni], A4[0][0].z, A4[0][1].z, A4[0][0].w, A4[0][1].w,
                     b.z, b.w);
            mma_tf32(c[1][ni], A4[1][0].z, A4[1][1].z, A4[1][0].w, A4[1][1].w,
                     b.z, b.w);
        }
        if (++rd == NSTG) rd = 0;
        if (++wr == NSTG) wr = 0;
    }

    // ---------------- epilogue ----------------
    float* __restrict__ dst;
    int colBase;
    if (MODE == 0) {
        const int sect = blockN >> 11;          // 0:Q 1:K 2:V
        dst = (sect == 0) ? g_Q : ((sect == 1) ? g_K : g_V);
        colBase = blockN & (D_ - 1);
    } else {
        dst = outParam;
        colBase = blockN;
    }

    #pragma unroll
    for (int mi = 0; mi < 2; ++mi) {
        const size_t rA = blockM + wm + mi * 16 + gID;
        const size_t rB = rA + 8;
        #pragma unroll
        for (int ni = 0; ni < 8; ++ni) {
            const int e  = blockN + wn + ni * 8 + tig * 2;
            const int el = colBase + wn + ni * 8 + tig * 2;
            const float bv0 = __ldg(&bias[e]);
            const float bv1 = __ldg(&bias[e + 1]);
            float2 v0 = make_float2(c[mi][ni][0] + bv0, c[mi][ni][1] + bv1);
            float2 v1 = make_float2(c[mi][ni][2] + bv0, c[mi][ni][3] + bv1);
            if (MODE == 1) {
                const float2 x0 = *(const float2*)(Xres + rA * D_ + el);
                const float2 x1 = *(const float2*)(Xres + rB * D_ + el);
                v0.x += x0.x; v0.y += x0.y;
                v1.x += x1.x; v1.y += x1.y;
            }
            *(float2*)(dst + rA * D_ + el) = v0;
            *(float2*)(dst + rB * D_ + el) = v1;
        }
    }
}

// -------- reduction stage 1: per (batch, chunk) partial of fm(rope(K)) * V ---
__global__ __launch_bounds__(256)
void reduce_A_kernel()
{
    const int b     = blockIdx.x >> 7;     // / NCHUNK
    const int chunk = blockIdx.x & (NCHUNK - 1);
    const int tid   = threadIdx.x;
    __shared__ float red[8];

    float acc[8];
    #pragma unroll
    for (int j = 0; j < 8; j++) acc[j] = 0.f;

    float invf[2];
    #pragma unroll
    for (int j = 0; j < 2; j++) {
        const int p = tid + 256 * j;
        invf[j] = exp2f((float)p * (float)NEG_L2T_OVER_512);
    }

    const int s0 = chunk * CHUNKS_S;
    for (int s = s0; s < s0 + CHUNKS_S; ++s) {
        const size_t rowoff = ((size_t)b * S_ + s) * D_;
        float kr[8];
        float sq = 0.f;
        #pragma unroll
        for (int j = 0; j < 4; ++j) {
            const int p = tid + 256 * j;
            const float2 kv = *(const float2*)(g_K + rowoff + 2 * p);
            float x0 = kv.x, x1 = kv.y;
            if (j < 2) {
                float sn, cs;
                sincosf((float)s * invf[j], &sn, &cs);
                const float r0 = x0 * cs - x1 * sn;
                const float r1 = x1 * cs + x0 * sn;
                x0 = r0; x1 = r1;
            }
            kr[2 * j] = x0; kr[2 * j + 1] = x1;
            sq = fmaf(x0, x0, fmaf(x1, x1, sq));
        }
        #pragma unroll
        for (int o = 16; o; o >>= 1) sq += __shfl_xor_sync(0xffffffffu, sq, o);
        if ((tid & 31) == 0) red[tid >> 5] = sq;
        __syncthreads();
        const float tot = red[0] + red[1] + red[2] + red[3]
                        + red[4] + red[5] + red[6] + red[7];
        __syncthreads();
        const float inv_n = 1.f / fmaxf(sqrtf(tot), 1e-12f);

        #pragma unroll
        for (int j = 0; j < 4; ++j) {
            const int p = tid + 256 * j;
            const float2 vv = *(const float2*)(g_V + rowoff + 2 * p);
            acc[2 * j]     = fmaf(kr[2 * j]     * inv_n, vv.x, acc[2 * j]);
            acc[2 * j + 1] = fmaf(kr[2 * j + 1] * inv_n, vv.y, acc[2 * j + 1]);
        }
    }
    float* dstp = g_Apart + ((size_t)b * NCHUNK + chunk) * D_;
    #pragma unroll
    for (int j = 0; j < 4; ++j) {
        const int p = tid + 256 * j;
        *(float2*)(dstp + 2 * p) = make_float2(acc[2 * j], acc[2 * j + 1]);
    }
}

// -------- reduction stage 2: fixed-order finalize ----------------------------
__global__ void finalize_A_kernel()
{
    const int i = blockIdx.x * 256 + threadIdx.x;   // i < B_*D_
    const int b = i >> 11;
    const int d = i & (D_ - 1);
    float s = 0.f;
    for (int c = 0; c < NCHUNK; ++c)
        s += g_Apart[((size_t)b * NCHUNK + c) * D_ + d];
    g_A[i] = s;
}

// -------- Yb = rna(A * rope(Q)), stored k-PERMUTED for GEMM2 ------------------
__global__ __launch_bounds__(256)
void yb_kernel()
{
    const int m = blockIdx.x;
    const int b = m >> 12;
    const int s = m & (S_ - 1);
    const int tid = threadIdx.x;
    const size_t rowoff = (size_t)m * D_;
    const float* Arow = g_A + b * D_;

    #pragma unroll
    for (int j = 0; j < 4; ++j) {
        const int p = tid + 256 * j;
        const float2 q = *(const float2*)(g_Q + rowoff + 2 * p);
        float x0 = q.x, x1 = q.y;
        if (j < 2) {
            const float invf = exp2f((float)p * (float)NEG_L2T_OVER_512);
            float sn, cs;
            sincosf((float)s * invf, &sn, &cs);
            const float r0 = x0 * cs - x1 * sn;
            const float r1 = x1 * cs + x0 * sn;
            x0 = r0; x1 = r1;
        }
        const float2 a = *(const float2*)(Arow + 2 * p);
        // permuted store: col c0=2p -> group g=p>>3, k=(2p)&15,
        // pos = g*16 + (k&3)*4 + (k>>2); col c0+1 lands at pos+4.
        const int g = p >> 3;
        const int k = (2 * p) & 15;
        const int pos0 = g * 16 + (k & 3) * 4 + (k >> 2);
        g_Yb[rowoff + pos0]     = __uint_as_float(f2tf32(a.x * x0));
        g_Yb[rowoff + pos0 + 4] = __uint_as_float(f2tf32(a.y * x1));
    }
}

// ---------------- launch ------------------------------------------------------
extern "C" void kernel_launch(void* const* d_in, const int* in_sizes, int n_in,
                              void* d_out, int out_size)
{
    const float* X     = (const float*)d_in[0];   // [8,4096,2048]
    const float* W_in  = (const float*)d_in[1];   // [6144,2048]
    const float* b_in  = (const float*)d_in[2];   // [6144]
    const float* W_out = (const float*)d_in[3];   // [2048,2048]
    const float* b_out = (const float*)d_in[4];   // [2048]
    float* out = (float*)d_out;

    float* xc; float* w1c; float* w2c;
    cudaGetSymbolAddress((void**)&xc,  g_Xc);
    cudaGetSymbolAddress((void**)&w1c, g_W1c);
    cudaGetSymbolAddress((void**)&w2c, g_W2c);

    // 0) pre-round to tf32 grid + permute k-groups
    round_perm_kernel<<<(M_ * (D_/4) + 255) / 256, 256>>>(X, xc, M_ * (D_/4));
    round_perm_kernel<<<((E1_ * (D_/4)) + 255) / 256, 256>>>(W_in, w1c, E1_ * (D_/4));
    round_perm_kernel<<<((D_ * (D_/4)) + 255) / 256, 256>>>(W_out, w2c, D_ * (D_/4));

    // 1) QKV = X @ W_in^T + b_in  ->  g_Q, g_K, g_V
    gemm_tf32<0><<<dim3(E1_ / BN, M_ / BM), 256>>>(w1c, b_in, nullptr, nullptr);

    // 2) A = sum_s fm(rope(K)) * V
    reduce_A_kernel<<<B_ * NCHUNK, 256>>>();
    finalize_A_kernel<<<(B_ * D_) / 256, 256>>>();

    // 3) Yb = rna(A ⊙ rope(Q))  (k-permuted layout)
    yb_kernel<<<M_, 256>>>();

    // 4) out = Yb @ W_out^T + b_out + X
    gemm_tf32<1><<<dim3(D_ / BN, M_ / BM), 256>>>(w2c, b_out, X, out);

    (void)in_sizes; (void)n_in; (void)out_size;
}

// round 6
// speedup vs baseline: 1.9769x; 1.0849x over previous
#include <cuda_runtime.h>
#include <cstdint>

// ---------------- problem constants ----------------
#define B_   8
#define S_   4096
#define D_   2048
#define M_   (B_*S_)        // 32768 tokens
#define E1_  (3*D_)         // 6144
#define NCHUNK 128
#define CHUNKS_S (S_/NCHUNK)   // 32

// ---------------- scratch (device globals) ----------------
__device__ float g_Q  [67108864];   // [M, D] fp32 (natural layout)
__device__ float g_K  [67108864];
__device__ float g_V  [67108864];
__device__ float g_Yb [67108864];   // rna-rounded + k-permuted (GEMM2 A input)
__device__ float g_Xc [67108864];   // rna(X), k-permuted
__device__ float g_W1c[(size_t)E1_ * D_];   // rna(W_in), k-permuted
__device__ float g_W2c[(size_t)D_ * D_];    // rna(W_out), k-permuted
__device__ float g_Apart[(size_t)B_ * NCHUNK * D_];
__device__ float g_A[B_ * D_];

#define NEG_L2T_OVER_512 (-0.025952563241307517)

// ---------------- PTX helpers ----------------
__device__ __forceinline__ void cp_async16(void* sdst, const void* gsrc) {
    unsigned saddr = (unsigned)__cvta_generic_to_shared(sdst);
    asm volatile("cp.async.cg.shared.global [%0], [%1], 16;" :: "r"(saddr), "l"(gsrc));
}
#define CP_COMMIT() asm volatile("cp.async.commit_group;")
#define CP_WAIT2()  asm volatile("cp.async.wait_group 2;")

__device__ __forceinline__ unsigned f2tf32(float x) {
    unsigned r;
    asm("cvt.rna.tf32.f32 %0, %1;" : "=r"(r) : "f"(x));
    return r;
}

__device__ __forceinline__ void mma_tf32(float c[4], unsigned a0, unsigned a1,
                                         unsigned a2, unsigned a3,
                                         unsigned b0, unsigned b1) {
    asm volatile(
        "mma.sync.aligned.m16n8k8.row.col.f32.tf32.tf32.f32 "
        "{%0,%1,%2,%3},{%4,%5,%6,%7},{%8,%9},{%0,%1,%2,%3};"
        : "+f"(c[0]), "+f"(c[1]), "+f"(c[2]), "+f"(c[3])
        : "r"(a0), "r"(a1), "r"(a2), "r"(a3), "r"(b0), "r"(b1));
}

// -------- pre-round to tf32 grid + permute within each 16-col group ----------
// perm(k) = (k&3)*4 + (k>>2) (involution): output chunk j of group g holds
// source k = {j, j+4, j+8, j+12}.
__global__ __launch_bounds__(256)
void round_perm_kernel(const float* __restrict__ src, float* __restrict__ dst,
                       int n4)
{
    const int c = blockIdx.x * 256 + threadIdx.x;
    if (c >= n4) return;
    const int g = c >> 2, j = c & 3;
    const float* s = src + (size_t)g * 16 + j;
    float4 o;
    o.x = __uint_as_float(f2tf32(s[0]));
    o.y = __uint_as_float(f2tf32(s[4]));
    o.z = __uint_as_float(f2tf32(s[8]));
    o.w = __uint_as_float(f2tf32(s[12]));
    ((float4*)dst)[c] = o;
}

// ---------------- TF32 GEMM: C[M,N] = A[M,K] * B[N,K]^T (+ epilogue) --------
// 4-stage cp.async pipeline, k-loop unrolled x4 so all stage indices are
// compile-time; global sources advance by pointer increment.
// MODE 0: A=g_Xc -> g_Q/g_K/g_V, bias=b_in.
// MODE 1: A=g_Yb -> d_out, epilogue adds b_out + X residual.
#define BM 128
#define BN 128
#define BK 16
#define LDSR 16                 // words/row (stride 16 mod 32 banks: conflict-free)
#define KT (D_/BK)              // 128
#define NSTG 4
#define STG_W (BM*LDSR)         // 2048 words per stage per operand
#define SM_BOFF (NSTG*STG_W)    // B region starts after 4 A stages
#define GEMM_SMEM (NSTG*STG_W*2*4)   // 65536 bytes

template <int MODE>
__global__ __launch_bounds__(256, 2)
void gemm_tf32(const float* __restrict__ Bg,
               const float* __restrict__ bias,
               const float* __restrict__ Xres,
               float* __restrict__ outParam)
{
    extern __shared__ float sm[];   // [A: 4 stages][B: 4 stages]

    const float* __restrict__ Ag = (MODE == 0) ? g_Xc : g_Yb;

    const int tid  = threadIdx.x;
    const int lane = tid & 31;
    const int warp = tid >> 5;
    const int wm   = (warp >> 1) * 32;   // 4 warps in M
    const int wn   = (warp & 1) * 64;    // 2 warps in N
    const int gID  = lane >> 2;          // 0..7
    const int tig  = lane & 3;           // 0..3

    const int    blockN = blockIdx.x * BN;
    const size_t blockM = (size_t)blockIdx.y * BM;

    const int ldRow = tid >> 2;          // 0..63
    const int ldCol = (tid & 3) * 4;     // word offset of 16B chunk

    // persistent global source pointers (advance by BK per staged tile)
    const float* gA0 = Ag + (blockM + ldRow) * D_ + ldCol;
    const float* gA1 = Ag + (blockM + ldRow + 64) * D_ + ldCol;
    const float* gB0 = Bg + ((size_t)blockN + ldRow) * D_ + ldCol;
    const float* gB1 = Bg + ((size_t)blockN + ldRow + 64) * D_ + ldCol;

    // smem staging word offsets (within a stage)
    const int stA0 = ldRow * LDSR + ldCol;
    const int stA1 = (ldRow + 64) * LDSR + ldCol;

    // fragment word offsets (within a stage)
    int aoff[2][2], boff[8];
    #pragma unroll
    for (int mi = 0; mi < 2; mi++)
        #pragma unroll
        for (int h = 0; h < 2; h++)
            aoff[mi][h] = (wm + mi * 16 + h * 8 + gID) * LDSR + tig * 4;
    #pragma unroll
    for (int ni = 0; ni < 8; ni++)
        boff[ni] = (wn + ni * 8 + gID) * LDSR + tig * 4;

    float c[2][8][4];
    #pragma unroll
    for (int i = 0; i < 2; i++)
        #pragma unroll
        for (int j = 0; j < 8; j++)
            #pragma unroll
            for (int k = 0; k < 4; k++) c[i][j][k] = 0.f;

    // prologue: stage tiles 0..2
    #pragma unroll
    for (int stg = 0; stg < 3; ++stg) {
        float* sA = sm + stg * STG_W;
        float* sB = sm + SM_BOFF + stg * STG_W;
        cp_async16(sA + stA0, gA0); cp_async16(sA + stA1, gA1);
        cp_async16(sB + stA0, gB0); cp_async16(sB + stA1, gB1);
        CP_COMMIT();
        gA0 += BK; gA1 += BK; gB0 += BK; gB1 += BK;
    }

    for (int kt = 0; kt < KT; kt += NSTG) {
        #pragma unroll
        for (int j = 0; j < NSTG; ++j) {
            // tile kt+j was committed 3 groups ago -> wait until <=2 pending
            CP_WAIT2();
            __syncthreads();
            // issue loads for tile kt+j+3 into stage (j+3)%4; that stage was
            // last read at compute kt+j-1, which every thread finished before
            // the barrier above.
            if (kt + j + 3 < KT) {
                float* sA = sm + ((j + 3) & 3) * STG_W;
                float* sB = sm + SM_BOFF + ((j + 3) & 3) * STG_W;
                cp_async16(sA + stA0, gA0); cp_async16(sA + stA1, gA1);
                cp_async16(sB + stA0, gB0); cp_async16(sB + stA1, gB1);
                gA0 += BK; gA1 += BK; gB0 += BK; gB1 += BK;
            }
            CP_COMMIT();

            const float* sA = sm + j * STG_W;
            const float* sB = sm + SM_BOFF + j * STG_W;

            uint4 A4[2][2];
            #pragma unroll
            for (int mi = 0; mi < 2; mi++)
                #pragma unroll
                for (int h = 0; h < 2; h++)
                    A4[mi][h] = *(const uint4*)(sA + aoff[mi][h]);

            #pragma unroll
            for (int ni = 0; ni < 8; ++ni) {
                const uint4 b = *(const uint4*)(sB + boff[ni]);
                mma_tf32(c[0][ni], A4[0][0].x, A4[0][1].x, A4[0][0].y, A4[0][1].y,
                         b.x, b.y);
                mma_tf32(c[1][ni], A4[1][0].x, A4[1][1].x, A4[1][0].y, A4[1][1].y,
                         b.x, b.y);
                mma_tf32(c[0][ni], A4[0][0].z, A4[0][1].z, A4[0][0].w, A4[0][1].w,
                         b.z, b.w);
                mma_tf32(c[1][ni], A4[1][0].z, A4[1][1].z, A4[1][0].w, A4[1][1].w,
                         b.z, b.w);
            }
        }
    }

    // ---------------- epilogue ----------------
    float* __restrict__ dst;
    int colBase;
    if (MODE == 0) {
        const int sect = blockN >> 11;          // 0:Q 1:K 2:V
        dst = (sect == 0) ? g_Q : ((sect == 1) ? g_K : g_V);
        colBase = blockN & (D_ - 1);
    } else {
        dst = outParam;
        colBase = blockN;
    }

    #pragma unroll
    for (int mi = 0; mi < 2; ++mi) {
        const size_t rA = blockM + wm + mi * 16 + gID;
        const size_t rB = rA + 8;
        #pragma unroll
        for (int ni = 0; ni < 8; ++ni) {
            const int e  = blockN + wn + ni * 8 + tig * 2;
            const int el = colBase + wn + ni * 8 + tig * 2;
            const float bv0 = __ldg(&bias[e]);
            const float bv1 = __ldg(&bias[e + 1]);
            float2 v0 = make_float2(c[mi][ni][0] + bv0, c[mi][ni][1] + bv1);
            float2 v1 = make_float2(c[mi][ni][2] + bv0, c[mi][ni][3] + bv1);
            if (MODE == 1) {
                const float2 x0 = *(const float2*)(Xres + rA * D_ + el);
                const float2 x1 = *(const float2*)(Xres + rB * D_ + el);
                v0.x += x0.x; v0.y += x0.y;
                v1.x += x1.x; v1.y += x1.y;
            }
            *(float2*)(dst + rA * D_ + el) = v0;
            *(float2*)(dst + rB * D_ + el) = v1;
        }
    }
}

// -------- reduction stage 1: per (batch, chunk) partial of fm(rope(K)) * V ---
__global__ __launch_bounds__(256)
void reduce_A_kernel()
{
    const int b     = blockIdx.x >> 7;
    const int chunk = blockIdx.x & (NCHUNK - 1);
    const int tid   = threadIdx.x;
    __shared__ float red[8];

    float acc[8];
    #pragma unroll
    for (int j = 0; j < 8; j++) acc[j] = 0.f;

    float invf[2];
    #pragma unroll
    for (int j = 0; j < 2; j++) {
        const int p = tid + 256 * j;
        invf[j] = exp2f((float)p * (float)NEG_L2T_OVER_512);
    }

    const int s0 = chunk * CHUNKS_S;
    for (int s = s0; s < s0 + CHUNKS_S; ++s) {
        const size_t rowoff = ((size_t)b * S_ + s) * D_;
        float kr[8];
        float sq = 0.f;
        #pragma unroll
        for (int j = 0; j < 4; ++j) {
            const int p = tid + 256 * j;
            const float2 kv = *(const float2*)(g_K + rowoff + 2 * p);
            float x0 = kv.x, x1 = kv.y;
            if (j < 2) {
                float sn, cs;
                sincosf((float)s * invf[j], &sn, &cs);
                const float r0 = x0 * cs - x1 * sn;
                const float r1 = x1 * cs + x0 * sn;
                x0 = r0; x1 = r1;
            }
            kr[2 * j] = x0; kr[2 * j + 1] = x1;
            sq = fmaf(x0, x0, fmaf(x1, x1, sq));
        }
        #pragma unroll
        for (int o = 16; o; o >>= 1) sq += __shfl_xor_sync(0xffffffffu, sq, o);
        if ((tid & 31) == 0) red[tid >> 5] = sq;
        __syncthreads();
        const float tot = red[0] + red[1] + red[2] + red[3]
                        + red[4] + red[5] + red[6] + red[7];
        __syncthreads();
        const float inv_n = 1.f / fmaxf(sqrtf(tot), 1e-12f);

        #pragma unroll
        for (int j = 0; j < 4; ++j) {
            const int p = tid + 256 * j;
            const float2 vv = *(const float2*)(g_V + rowoff + 2 * p);
            acc[2 * j]     = fmaf(kr[2 * j]     * inv_n, vv.x, acc[2 * j]);
            acc[2 * j + 1] = fmaf(kr[2 * j + 1] * inv_n, vv.y, acc[2 * j + 1]);
        }
    }
    float* dstp = g_Apart + ((size_t)b * NCHUNK + chunk) * D_;
    #pragma unroll
    for (int j = 0; j < 4; ++j) {
        const int p = tid + 256 * j;
        *(float2*)(dstp + 2 * p) = make_float2(acc[2 * j], acc[2 * j + 1]);
    }
}

// -------- reduction stage 2: fixed-order finalize ----------------------------
__global__ void finalize_A_kernel()
{
    const int i = blockIdx.x * 256 + threadIdx.x;
    const int b = i >> 11;
    const int d = i & (D_ - 1);
    float s = 0.f;
    for (int c = 0; c < NCHUNK; ++c)
        s += g_Apart[((size_t)b * NCHUNK + c) * D_ + d];
    g_A[i] = s;
}

// -------- Yb = rna(A * rope(Q)), stored k-PERMUTED for GEMM2 ------------------
__global__ __launch_bounds__(256)
void yb_kernel()
{
    const int m = blockIdx.x;
    const int b = m >> 12;
    const int s = m & (S_ - 1);
    const int tid = threadIdx.x;
    const size_t rowoff = (size_t)m * D_;
    const float* Arow = g_A + b * D_;

    #pragma unroll
    for (int j = 0; j < 4; ++j) {
        const int p = tid + 256 * j;
        const float2 q = *(const float2*)(g_Q + rowoff + 2 * p);
        float x0 = q.x, x1 = q.y;
        if (j < 2) {
            const float invf = exp2f((float)p * (float)NEG_L2T_OVER_512);
            float sn, cs;
            sincosf((float)s * invf, &sn, &cs);
            const float r0 = x0 * cs - x1 * sn;
            const float r1 = x1 * cs + x0 * sn;
            x0 = r0; x1 = r1;
        }
        const float2 a = *(const float2*)(Arow + 2 * p);
        const int g = p >> 3;
        const int k = (2 * p) & 15;
        const int pos0 = g * 16 + (k & 3) * 4 + (k >> 2);
        g_Yb[rowoff + pos0]     = __uint_as_float(f2tf32(a.x * x0));
        g_Yb[rowoff + pos0 + 4] = __uint_as_float(f2tf32(a.y * x1));
    }
}

// ---------------- launch ------------------------------------------------------
extern "C" void kernel_launch(void* const* d_in, const int* in_sizes, int n_in,
                              void* d_out, int out_size)
{
    const float* X     = (const float*)d_in[0];   // [8,4096,2048]
    const float* W_in  = (const float*)d_in[1];   // [6144,2048]
    const float* b_in  = (const float*)d_in[2];   // [6144]
    const float* W_out = (const float*)d_in[3];   // [2048,2048]
    const float* b_out = (const float*)d_in[4];   // [2048]
    float* out = (float*)d_out;

    float* xc; float* w1c; float* w2c;
    cudaGetSymbolAddress((void**)&xc,  g_Xc);
    cudaGetSymbolAddress((void**)&w1c, g_W1c);
    cudaGetSymbolAddress((void**)&w2c, g_W2c);

    cudaFuncSetAttribute(gemm_tf32<0>, cudaFuncAttributeMaxDynamicSharedMemorySize, GEMM_SMEM);
    cudaFuncSetAttribute(gemm_tf32<1>, cudaFuncAttributeMaxDynamicSharedMemorySize, GEMM_SMEM);

    // 0) pre-round to tf32 grid + permute k-groups
    round_perm_kernel<<<(M_ * (D_/4) + 255) / 256, 256>>>(X, xc, M_ * (D_/4));
    round_perm_kernel<<<((E1_ * (D_/4)) + 255) / 256, 256>>>(W_in, w1c, E1_ * (D_/4));
    round_perm_kernel<<<((D_ * (D_/4)) + 255) / 256, 256>>>(W_out, w2c, D_ * (D_/4));

    // 1) QKV = X @ W_in^T + b_in  ->  g_Q, g_K, g_V
    gemm_tf32<0><<<dim3(E1_ / BN, M_ / BM), 256, GEMM_SMEM>>>(w1c, b_in, nullptr, nullptr);

    // 2) A = sum_s fm(rope(K)) * V
    reduce_A_kernel<<<B_ * NCHUNK, 256>>>();
    finalize_A_kernel<<<(B_ * D_) / 256, 256>>>();

    // 3) Yb = rna(A ⊙ rope(Q))  (k-permuted layout)
    yb_kernel<<<M_, 256>>>();

    // 4) out = Yb @ W_out^T + b_out + X
    gemm_tf32<1><<<dim3(D_ / BN, M_ / BM), 256, GEMM_SMEM>>>(w2c, b_out, X, out);

    (void)in_sizes; (void)n_in; (void)out_size;
}

// round 7
// speedup vs baseline: 2.0074x; 1.0154x over previous
#include <cuda_runtime.h>
#include <cstdint>

// ---------------- problem constants ----------------
#define B_   8
#define S_   4096
#define D_   2048
#define M_   (B_*S_)        // 32768 tokens
#define E1_  (3*D_)         // 6144
#define NCHUNK 128
#define CHUNKS_S (S_/NCHUNK)   // 32

// ---------------- scratch (device globals) ----------------
__device__ float g_Q  [67108864];   // [M, D] fp32 (natural layout)
__device__ float g_K  [67108864];
__device__ float g_V  [67108864];
__device__ float g_Yb [67108864];   // rna-rounded + k-permuted (GEMM2 A input)
__device__ float g_Xc [67108864];   // rna(X), k-permuted
__device__ float g_W1c[(size_t)E1_ * D_];   // rna(W_in), k-permuted
__device__ float g_W2c[(size_t)D_ * D_];    // rna(W_out), k-permuted
__device__ float g_Apart[(size_t)B_ * NCHUNK * D_];
__device__ float g_A[B_ * D_];

#define NEG_L2T_OVER_512 (-0.025952563241307517)

// ---------------- PTX helpers ----------------
__device__ __forceinline__ void cp_async16(void* sdst, const void* gsrc) {
    unsigned saddr = (unsigned)__cvta_generic_to_shared(sdst);
    asm volatile("cp.async.cg.shared.global [%0], [%1], 16;" :: "r"(saddr), "l"(gsrc));
}
#define CP_COMMIT() asm volatile("cp.async.commit_group;")
#define CP_WAIT1()  asm volatile("cp.async.wait_group 1;")

__device__ __forceinline__ unsigned f2tf32(float x) {
    unsigned r;
    asm("cvt.rna.tf32.f32 %0, %1;" : "=r"(r) : "f"(x));
    return r;
}

__device__ __forceinline__ void mma_tf32(float c[4], unsigned a0, unsigned a1,
                                         unsigned a2, unsigned a3,
                                         unsigned b0, unsigned b1) {
    asm volatile(
        "mma.sync.aligned.m16n8k8.row.col.f32.tf32.tf32.f32 "
        "{%0,%1,%2,%3},{%4,%5,%6,%7},{%8,%9},{%0,%1,%2,%3};"
        : "+f"(c[0]), "+f"(c[1]), "+f"(c[2]), "+f"(c[3])
        : "r"(a0), "r"(a1), "r"(a2), "r"(a3), "r"(b0), "r"(b1));
}

// -------- pre-round to tf32 grid + permute within each 16-col group ----------
// perm(k) = (k&3)*4 + (k>>2) (involution): output chunk j of group g holds
// source k = {j, j+4, j+8, j+12}.
__global__ __launch_bounds__(256)
void round_perm_kernel(const float* __restrict__ src, float* __restrict__ dst,
                       int n4)
{
    const int c = blockIdx.x * 256 + threadIdx.x;
    if (c >= n4) return;
    const int g = c >> 2, j = c & 3;
    const float* s = src + (size_t)g * 16 + j;
    float4 o;
    o.x = __uint_as_float(f2tf32(s[0]));
    o.y = __uint_as_float(f2tf32(s[4]));
    o.z = __uint_as_float(f2tf32(s[8]));
    o.w = __uint_as_float(f2tf32(s[12]));
    ((float4*)dst)[c] = o;
}

// ---------------- TF32 GEMM: C[M,N] = A[M,K] * B[N,K]^T (+ epilogue) --------
// BK=32 (two 16-wide sub-tiles per stage, each in the conflict-free LDSR=16
// layout). 3-stage cp.async pipeline; all stage indices compile-time via a
// 3-unrolled loop; global sources advance by pointer increment.
// MODE 0: A=g_Xc -> g_Q/g_K/g_V, bias=b_in.
// MODE 1: A=g_Yb -> d_out, epilogue adds b_out + X residual.
#define BM 128
#define BN 128
#define BK 32
#define KT (D_/BK)              // 64
#define NSTG 3
#define SUB_W 2048              // words per 16-wide sub-tile (128 rows x 16)
#define STG_W (2*SUB_W)         // 4096 words per stage per operand
#define SM_BOFF (NSTG*STG_W)    // B region after 3 A stages
#define GEMM_SMEM (NSTG*STG_W*2*4)   // 98304 bytes

template <int MODE>
__global__ __launch_bounds__(256, 2)
void gemm_tf32(const float* __restrict__ Bg,
               const float* __restrict__ bias,
               const float* __restrict__ Xres,
               float* __restrict__ outParam)
{
    extern __shared__ float sm[];

    const float* __restrict__ Ag = (MODE == 0) ? g_Xc : g_Yb;

    const int tid  = threadIdx.x;
    const int lane = tid & 31;
    const int warp = tid >> 5;
    const int wm   = (warp >> 1) * 32;   // 4 warps in M
    const int wn   = (warp & 1) * 64;    // 2 warps in N
    const int gID  = lane >> 2;          // 0..7
    const int tig  = lane & 3;           // 0..3

    const int    blockN = blockIdx.x * BN;
    const size_t blockM = (size_t)blockIdx.y * BM;

    const int ldRow = tid >> 2;          // 0..63
    const int ldCol = (tid & 3) * 4;     // word offset of 16B chunk

    // persistent global source pointers (advance by BK per staged tile)
    const float* gA0 = Ag + (blockM + ldRow) * D_ + ldCol;
    const float* gA1 = Ag + (blockM + ldRow + 64) * D_ + ldCol;
    const float* gB0 = Bg + ((size_t)blockN + ldRow) * D_ + ldCol;
    const float* gB1 = Bg + ((size_t)blockN + ldRow + 64) * D_ + ldCol;

    // smem staging word offsets (within a stage, sub-tile 0; sub1 at +SUB_W)
    const int stA0 = ldRow * 16 + ldCol;
    const int stA1 = (ldRow + 64) * 16 + ldCol;

    // fragment word offsets (within a sub-tile)
    int aoff[2][2], boff[8];
    #pragma unroll
    for (int mi = 0; mi < 2; mi++)
        #pragma unroll
        for (int h = 0; h < 2; h++)
            aoff[mi][h] = (wm + mi * 16 + h * 8 + gID) * 16 + tig * 4;
    #pragma unroll
    for (int ni = 0; ni < 8; ni++)
        boff[ni] = (wn + ni * 8 + gID) * 16 + tig * 4;

    float c[2][8][4];
    #pragma unroll
    for (int i = 0; i < 2; i++)
        #pragma unroll
        for (int j = 0; j < 8; j++)
            #pragma unroll
            for (int k = 0; k < 4; k++) c[i][j][k] = 0.f;

    // ---- stage loader (S compile-time after unroll) ----
    #define STAGE_LOAD(S)                                                    \
        do {                                                                 \
            float* sA = sm + (S) * STG_W;                                    \
            float* sB = sm + SM_BOFF + (S) * STG_W;                          \
            cp_async16(sA + stA0,         gA0);                              \
            cp_async16(sA + stA0 + SUB_W, gA0 + 16);                         \
            cp_async16(sA + stA1,         gA1);                              \
            cp_async16(sA + stA1 + SUB_W, gA1 + 16);                         \
            cp_async16(sB + stA0,         gB0);                              \
            cp_async16(sB + stA0 + SUB_W, gB0 + 16);                         \
            cp_async16(sB + stA1,         gB1);                              \
            cp_async16(sB + stA1 + SUB_W, gB1 + 16);                         \
            gA0 += BK; gA1 += BK; gB0 += BK; gB1 += BK;                      \
        } while (0)

    #define STAGE_COMPUTE(S)                                                 \
        do {                                                                 \
            const float* sA = sm + (S) * STG_W;                              \
            const float* sB = sm + SM_BOFF + (S) * STG_W;                    \
            _Pragma("unroll")                                                \
            for (int kg = 0; kg < 2; ++kg) {                                 \
                const float* a0 = sA + kg * SUB_W;                           \
                const float* b0 = sB + kg * SUB_W;                           \
                uint4 A4[2][2];                                              \
                _Pragma("unroll")                                            \
                for (int mi = 0; mi < 2; mi++)                               \
                    _Pragma("unroll")                                        \
                    for (int h = 0; h < 2; h++)                              \
                        A4[mi][h] = *(const uint4*)(a0 + aoff[mi][h]);       \
                _Pragma("unroll")                                            \
                for (int ni = 0; ni < 8; ++ni) {                             \
                    const uint4 b = *(const uint4*)(b0 + boff[ni]);          \
                    mma_tf32(c[0][ni], A4[0][0].x, A4[0][1].x,               \
                             A4[0][0].y, A4[0][1].y, b.x, b.y);              \
                    mma_tf32(c[1][ni], A4[1][0].x, A4[1][1].x,               \
                             A4[1][0].y, A4[1][1].y, b.x, b.y);              \
                    mma_tf32(c[0][ni], A4[0][0].z, A4[0][1].z,               \
                             A4[0][0].w, A4[0][1].w, b.z, b.w);              \
                    mma_tf32(c[1][ni], A4[1][0].z, A4[1][1].z,               \
                             A4[1][0].w, A4[1][1].w, b.z, b.w);              \
                }                                                            \
            }                                                                \
        } while (0)

    // prologue: tiles 0,1 -> stages 0,1 (one commit group each)
    STAGE_LOAD(0); CP_COMMIT();
    STAGE_LOAD(1); CP_COMMIT();

    // main: tiles 0..62 in 21 triples; tile k lives in stage k%3.
    for (int t = 0; t < 21; ++t) {
        #pragma unroll
        for (int jj = 0; jj < 3; ++jj) {
            const int k = 3 * t + jj;
            CP_WAIT1();            // tile k's group (committed 2 back) done
            __syncthreads();       // stage (jj+2)%3 fully consumed (tile k-1)
            if (k + 2 < KT) STAGE_LOAD((jj + 2) % 3);
            CP_COMMIT();
            STAGE_COMPUTE(jj);
        }
    }
    // tail: tile 63 (stage 0)
    CP_WAIT1();
    __syncthreads();
    STAGE_COMPUTE(0);

    #undef STAGE_LOAD
    #undef STAGE_COMPUTE

    // ---------------- epilogue ----------------
    float* __restrict__ dst;
    int colBase;
    if (MODE == 0) {
        const int sect = blockN >> 11;          // 0:Q 1:K 2:V
        dst = (sect == 0) ? g_Q : ((sect == 1) ? g_K : g_V);
        colBase = blockN & (D_ - 1);
    } else {
        dst = outParam;
        colBase = blockN;
    }

    #pragma unroll
    for (int mi = 0; mi < 2; ++mi) {
        const size_t rA = blockM + wm + mi * 16 + gID;
        const size_t rB = rA + 8;
        #pragma unroll
        for (int ni = 0; ni < 8; ++ni) {
            const int e  = blockN + wn + ni * 8 + tig * 2;
            const int el = colBase + wn + ni * 8 + tig * 2;
            const float bv0 = __ldg(&bias[e]);
            const float bv1 = __ldg(&bias[e + 1]);
            float2 v0 = make_float2(c[mi][ni][0] + bv0, c[mi][ni][1] + bv1);
            float2 v1 = make_float2(c[mi][ni][2] + bv0, c[mi][ni][3] + bv1);
            if (MODE == 1) {
                const float2 x0 = *(const float2*)(Xres + rA * D_ + el);
                const float2 x1 = *(const float2*)(Xres + rB * D_ + el);
                v0.x += x0.x; v0.y += x0.y;
                v1.x += x1.x; v1.y += x1.y;
            }
            *(float2*)(dst + rA * D_ + el) = v0;
            *(float2*)(dst + rB * D_ + el) = v1;
        }
    }
}

// -------- reduction stage 1: per (batch, chunk) partial of fm(rope(K)) * V ---
__global__ __launch_bounds__(256)
void reduce_A_kernel()
{
    const int b     = blockIdx.x >> 7;
    const int chunk = blockIdx.x & (NCHUNK - 1);
    const int tid   = threadIdx.x;
    __shared__ float red[8];

    float acc[8];
    #pragma unroll
    for (int j = 0; j < 8; j++) acc[j] = 0.f;

    float invf[2];
    #pragma unroll
    for (int j = 0; j < 2; j++) {
        const int p = tid + 256 * j;
        invf[j] = exp2f((float)p * (float)NEG_L2T_OVER_512);
    }

    const int s0 = chunk * CHUNKS_S;
    for (int s = s0; s < s0 + CHUNKS_S; ++s) {
        const size_t rowoff = ((size_t)b * S_ + s) * D_;
        float kr[8];
        float sq = 0.f;
        #pragma unroll
        for (int j = 0; j < 4; ++j) {
            const int p = tid + 256 * j;
            const float2 kv = *(const float2*)(g_K + rowoff + 2 * p);
            float x0 = kv.x, x1 = kv.y;
            if (j < 2) {
                float sn, cs;
                sincosf((float)s * invf[j], &sn, &cs);
                const float r0 = x0 * cs - x1 * sn;
                const float r1 = x1 * cs + x0 * sn;
                x0 = r0; x1 = r1;
            }
            kr[2 * j] = x0; kr[2 * j + 1] = x1;
            sq = fmaf(x0, x0, fmaf(x1, x1, sq));
        }
        #pragma unroll
        for (int o = 16; o; o >>= 1) sq += __shfl_xor_sync(0xffffffffu, sq, o);
        if ((tid & 31) == 0) red[tid >> 5] = sq;
        __syncthreads();
        const float tot = red[0] + red[1] + red[2] + red[3]
                        + red[4] + red[5] + red[6] + red[7];
        __syncthreads();
        const float inv_n = 1.f / fmaxf(sqrtf(tot), 1e-12f);

        #pragma unroll
        for (int j = 0; j < 4; ++j) {
            const int p = tid + 256 * j;
            const float2 vv = *(const float2*)(g_V + rowoff + 2 * p);
            acc[2 * j]     = fmaf(kr[2 * j]     * inv_n, vv.x, acc[2 * j]);
            acc[2 * j + 1] = fmaf(kr[2 * j + 1] * inv_n, vv.y, acc[2 * j + 1]);
        }
    }
    float* dstp = g_Apart + ((size_t)b * NCHUNK + chunk) * D_;
    #pragma unroll
    for (int j = 0; j < 4; ++j) {
        const int p = tid + 256 * j;
        *(float2*)(dstp + 2 * p) = make_float2(acc[2 * j], acc[2 * j + 1]);
    }
}

// -------- reduction stage 2: fixed-order finalize ----------------------------
__global__ void finalize_A_kernel()
{
    const int i = blockIdx.x * 256 + threadIdx.x;
    const int b = i >> 11;
    const int d = i & (D_ - 1);
    float s = 0.f;
    for (int c = 0; c < NCHUNK; ++c)
        s += g_Apart[((size_t)b * NCHUNK + c) * D_ + d];
    g_A[i] = s;
}

// -------- Yb = rna(A * rope(Q)), stored k-PERMUTED for GEMM2 ------------------
__global__ __launch_bounds__(256)
void yb_kernel()
{
    const int m = blockIdx.x;
    const int b = m >> 12;
    const int s = m & (S_ - 1);
    const int tid = threadIdx.x;
    const size_t rowoff = (size_t)m * D_;
    const float* Arow = g_A + b * D_;

    #pragma unroll
    for (int j = 0; j < 4; ++j) {
        const int p = tid + 256 * j;
        const float2 q = *(const float2*)(g_Q + rowoff + 2 * p);
        float x0 = q.x, x1 = q.y;
        if (j < 2) {
            const float invf = exp2f((float)p * (float)NEG_L2T_OVER_512);
            float sn, cs;
            sincosf((float)s * invf, &sn, &cs);
            const float r0 = x0 * cs - x1 * sn;
            const float r1 = x1 * cs + x0 * sn;
            x0 = r0; x1 = r1;
        }
        const float2 a = *(const float2*)(Arow + 2 * p);
        const int g = p >> 3;
        const int k = (2 * p) & 15;
        const int pos0 = g * 16 + (k & 3) * 4 + (k >> 2);
        g_Yb[rowoff + pos0]     = __uint_as_float(f2tf32(a.x * x0));
        g_Yb[rowoff + pos0 + 4] = __uint_as_float(f2tf32(a.y * x1));
    }
}

// ---------------- launch ------------------------------------------------------
extern "C" void kernel_launch(void* const* d_in, const int* in_sizes, int n_in,
                              void* d_out, int out_size)
{
    const float* X     = (const float*)d_in[0];   // [8,4096,2048]
    const float* W_in  = (const float*)d_in[1];   // [6144,2048]
    const float* b_in  = (const float*)d_in[2];   // [6144]
    const float* W_out = (const float*)d_in[3];   // [2048,2048]
    const float* b_out = (const float*)d_in[4];   // [2048]
    float* out = (float*)d_out;

    float* xc; float* w1c; float* w2c;
    cudaGetSymbolAddress((void**)&xc,  g_Xc);
    cudaGetSymbolAddress((void**)&w1c, g_W1c);
    cudaGetSymbolAddress((void**)&w2c, g_W2c);

    cudaFuncSetAttribute(gemm_tf32<0>, cudaFuncAttributeMaxDynamicSharedMemorySize, GEMM_SMEM);
    cudaFuncSetAttribute(gemm_tf32<1>, cudaFuncAttributeMaxDynamicSharedMemorySize, GEMM_SMEM);

    // 0) pre-round to tf32 grid + permute k-groups
    round_perm_kernel<<<(M_ * (D_/4) + 255) / 256, 256>>>(X, xc, M_ * (D_/4));
    round_perm_kernel<<<((E1_ * (D_/4)) + 255) / 256, 256>>>(W_in, w1c, E1_ * (D_/4));
    round_perm_kernel<<<((D_ * (D_/4)) + 255) / 256, 256>>>(W_out, w2c, D_ * (D_/4));

    // 1) QKV = X @ W_in^T + b_in  ->  g_Q, g_K, g_V
    gemm_tf32<0><<<dim3(E1_ / BN, M_ / BM), 256, GEMM_SMEM>>>(w1c, b_in, nullptr, nullptr);

    // 2) A = sum_s fm(rope(K)) * V
    reduce_A_kernel<<<B_ * NCHUNK, 256>>>();
    finalize_A_kernel<<<(B_ * D_) / 256, 256>>>();

    // 3) Yb = rna(A ⊙ rope(Q))  (k-permuted layout)
    yb_kernel<<<M_, 256>>>();

    // 4) out = Yb @ W_out^T + b_out + X
    gemm_tf32<1><<<dim3(D_ / BN, M_ / BM), 256, GEMM_SMEM>>>(w2c, b_out, X, out);

    (void)in_sizes; (void)n_in; (void)out_size;
}

// round 8
// speedup vs baseline: 3.8175x; 1.9017x over previous
#include <cuda_runtime.h>
#include <cuda_fp16.h>
#include <cstdint>

// ---------------- problem constants ----------------
#define B_   8
#define S_   4096
#define D_   2048
#define M_   (B_*S_)        // 32768 tokens
#define E1_  (3*D_)         // 6144
#define NCHUNK 128
#define CHUNKS_S (S_/NCHUNK)   // 32

// ---------------- scratch (device globals) ----------------
__device__ float  g_Q  [67108864];   // [M, D] fp32
__device__ float  g_K  [67108864];
__device__ float  g_V  [67108864];
__device__ __half g_Yh [67108864];   // fp16, pair-permuted (GEMM2 A)
__device__ __half g_Xh [67108864];   // fp16(X), pair-permuted
__device__ __half g_W1h[(size_t)E1_ * D_];   // fp16(W_in), pair-permuted
__device__ __half g_W2h[(size_t)D_ * D_];    // fp16(W_out), pair-permuted
__device__ float  g_Apart[(size_t)B_ * NCHUNK * D_];
__device__ float  g_A[B_ * D_];

#define NEG_L2T_OVER_512 (-0.025952563241307517)

// ---------------- PTX helpers ----------------
__device__ __forceinline__ void cp_async16(void* sdst, const void* gsrc) {
    unsigned saddr = (unsigned)__cvta_generic_to_shared(sdst);
    asm volatile("cp.async.cg.shared.global [%0], [%1], 16;" :: "r"(saddr), "l"(gsrc));
}
#define CP_COMMIT() asm volatile("cp.async.commit_group;")
#define CP_WAIT2()  asm volatile("cp.async.wait_group 2;")

__device__ __forceinline__ unsigned pack_h2(float lo, float hi) {
    __half2 h = __floats2half2_rn(lo, hi);
    return *(unsigned*)&h;
}

__device__ __forceinline__ void mma_f16(float c[4], unsigned a0, unsigned a1,
                                        unsigned a2, unsigned a3,
                                        unsigned b0, unsigned b1) {
    asm volatile(
        "mma.sync.aligned.m16n8k16.row.col.f32.f16.f16.f32 "
        "{%0,%1,%2,%3},{%4,%5,%6,%7},{%8,%9},{%0,%1,%2,%3};"
        : "+f"(c[0]), "+f"(c[1]), "+f"(c[2]), "+f"(c[3])
        : "r"(a0), "r"(a1), "r"(a2), "r"(a3), "r"(b0), "r"(b1));
}

// -------- fp32 -> permuted fp16 ------------------------------------------------
// Within each 32-wide k-group: pair p (cols 2p,2p+1), kg = p/8, pp = p%8.
// slot(kg,pp) = (pp&3)*4 + (pp>>2) + 2*kg  (pairs; 16 slots per group).
// Output 16B chunk q (q=0..3) of a group holds slots 4q..4q+3:
//   j=0: kg0 pair q ; j=1: kg0 pair q+4 ; j=2: kg1 pair q ; j=3: kg1 pair q+4.
__global__ __launch_bounds__(256)
void half_perm_kernel(const float* __restrict__ src, __half* __restrict__ dst,
                      int n16)   // element count / 8
{
    const int c = blockIdx.x * 256 + threadIdx.x;
    if (c >= n16) return;
    const int row = c >> 8;           // D_/8 = 256 chunks per row
    const int cc  = c & 255;
    const int G   = cc >> 2;
    const int q   = cc & 3;
    const float* s = src + (size_t)row * D_ + G * 32 + q * 2;
    // k offsets for the 4 slots: kg*16 + p*2 with p = q, q+4 (kg 0 then 1)
    uint4 o;
    o.x = pack_h2(s[0],      s[1]);        // kg0, p=q
    o.y = pack_h2(s[8],      s[9]);        // kg0, p=q+4
    o.z = pack_h2(s[16],     s[17]);       // kg1, p=q
    o.w = pack_h2(s[24],     s[25]);       // kg1, p=q+4
    ((uint4*)dst)[c] = o;
}

// ---------------- FP16 GEMM: C[M,N] = A[M,K] * B[N,K]^T (+ epilogue) --------
// BK=32 k per stage; stage = 128 rows x 64B per operand (8 KB).
// 4-stage cp.async pipeline, stage indices compile-time (unroll 4).
// MODE 0: A=g_Xh -> g_Q/g_K/g_V, bias=b_in.
// MODE 1: A=g_Yh -> d_out, epilogue adds b_out + X residual.
#define BM 128
#define BN 128
#define BK 32
#define KT (D_/BK)              // 64
#define NSTG 4
#define STG_U4 512              // uint4 per stage per operand (128 rows x 4)
#define SM_BOFF (NSTG*STG_U4)   // B region after 4 A stages
#define GEMM_SMEM (NSTG*STG_U4*2*16)   // 65536 bytes

template <int MODE>
__global__ __launch_bounds__(256, 2)
void gemm_f16(const __half* __restrict__ Bg,
              const float* __restrict__ bias,
              const float* __restrict__ Xres,
              float* __restrict__ outParam)
{
    extern __shared__ uint4 sm4[];

    const __half* __restrict__ Ag = (MODE == 0) ? g_Xh : g_Yh;

    const int tid  = threadIdx.x;
    const int lane = tid & 31;
    const int warp = tid >> 5;
    const int wm   = (warp >> 1) * 32;   // 4 warps in M
    const int wn   = (warp & 1) * 64;    // 2 warps in N
    const int gID  = lane >> 2;          // 0..7
    const int tig  = lane & 3;           // 0..3

    const int    blockN = blockIdx.x * BN;
    const size_t blockM = (size_t)blockIdx.y * BM;

    // staging: 512 chunks per operand per stage; thread owns chunks tid, tid+256
    const int ldRow = tid >> 2;          // 0..63
    const int ldSub = tid & 3;           // 16B chunk within row (4 per row)

    // persistent global pointers (halves); advance 32 per staged tile
    const __half* gA0 = Ag + (blockM + ldRow) * D_ + ldSub * 8;
    const __half* gA1 = Ag + (blockM + ldRow + 64) * D_ + ldSub * 8;
    const __half* gB0 = Bg + ((size_t)blockN + ldRow) * D_ + ldSub * 8;
    const __half* gB1 = Bg + ((size_t)blockN + ldRow + 64) * D_ + ldSub * 8;

    // smem chunk offsets within a stage (uint4 units)
    const int stA0 = ldRow * 4 + ldSub;
    const int stA1 = (ldRow + 64) * 4 + ldSub;

    // fragment uint4 offsets within a stage
    int aoff[2][2], boff[8];
    #pragma unroll
    for (int mi = 0; mi < 2; mi++)
        #pragma unroll
        for (int h = 0; h < 2; h++)
            aoff[mi][h] = (wm + mi * 16 + h * 8 + gID) * 4 + tig;
    #pragma unroll
    for (int ni = 0; ni < 8; ni++)
        boff[ni] = (wn + ni * 8 + gID) * 4 + tig;

    float c[2][8][4];
    #pragma unroll
    for (int i = 0; i < 2; i++)
        #pragma unroll
        for (int j = 0; j < 8; j++)
            #pragma unroll
            for (int k = 0; k < 4; k++) c[i][j][k] = 0.f;

    #define STAGE_LOAD(S)                                                    \
        do {                                                                 \
            uint4* sA = sm4 + (S) * STG_U4;                                  \
            uint4* sB = sm4 + SM_BOFF + (S) * STG_U4;                        \
            cp_async16(sA + stA0, gA0);                                      \
            cp_async16(sA + stA1, gA1);                                      \
            cp_async16(sB + stA0, gB0);                                      \
            cp_async16(sB + stA1, gB1);                                      \
            gA0 += BK; gA1 += BK; gB0 += BK; gB1 += BK;                      \
        } while (0)

    // uint4 layout: .x = kg0 pair(t), .y = kg0 pair(t+4),
    //               .z = kg1 pair(t), .w = kg1 pair(t+4)
    #define STAGE_COMPUTE(S)                                                 \
        do {                                                                 \
            const uint4* sA = sm4 + (S) * STG_U4;                            \
            const uint4* sB = sm4 + SM_BOFF + (S) * STG_U4;                  \
            uint4 A4[2][2];                                                  \
            _Pragma("unroll")                                                \
            for (int mi = 0; mi < 2; mi++)                                   \
                _Pragma("unroll")                                            \
                for (int h = 0; h < 2; h++)                                  \
                    A4[mi][h] = sA[aoff[mi][h]];                             \
            _Pragma("unroll")                                                \
            for (int ni = 0; ni < 8; ++ni) {                                 \
                const uint4 b = sB[boff[ni]];                                \
                mma_f16(c[0][ni], A4[0][0].x, A4[0][1].x,                    \
                        A4[0][0].y, A4[0][1].y, b.x, b.y);                   \
                mma_f16(c[1][ni], A4[1][0].x, A4[1][1].x,                    \
                        A4[1][0].y, A4[1][1].y, b.x, b.y);                   \
                mma_f16(c[0][ni], A4[0][0].z, A4[0][1].z,                    \
                        A4[0][0].w, A4[0][1].w, b.z, b.w);                   \
                mma_f16(c[1][ni], A4[1][0].z, A4[1][1].z,                    \
                        A4[1][0].w, A4[1][1].w, b.z, b.w);                   \
            }                                                                \
        } while (0)

    // prologue: tiles 0..2 -> stages 0..2
    STAGE_LOAD(0); CP_COMMIT();
    STAGE_LOAD(1); CP_COMMIT();
    STAGE_LOAD(2); CP_COMMIT();

    // main: 64 tiles, tile k in stage k%4; at iter k load tile k+3.
    for (int t = 0; t < KT / NSTG; ++t) {
        #pragma unroll
        for (int jj = 0; jj < NSTG; ++jj) {
            const int k = NSTG * t + jj;
            CP_WAIT2();            // tile k's group (committed 3 back) done
            __syncthreads();       // stage (jj+3)%4 fully consumed (tile k-1)
            if (k + 3 < KT) STAGE_LOAD((jj + 3) & 3);
            CP_COMMIT();
            STAGE_COMPUTE(jj);
        }
    }

    #undef STAGE_LOAD
    #undef STAGE_COMPUTE

    // ---------------- epilogue ----------------
    float* __restrict__ dst;
    int colBase;
    if (MODE == 0) {
        const int sect = blockN >> 11;          // 0:Q 1:K 2:V
        dst = (sect == 0) ? g_Q : ((sect == 1) ? g_K : g_V);
        colBase = blockN & (D_ - 1);
    } else {
        dst = outParam;
        colBase = blockN;
    }

    #pragma unroll
    for (int mi = 0; mi < 2; ++mi) {
        const size_t rA = blockM + wm + mi * 16 + gID;
        const size_t rB = rA + 8;
        #pragma unroll
        for (int ni = 0; ni < 8; ++ni) {
            const int e  = blockN + wn + ni * 8 + tig * 2;
            const int el = colBase + wn + ni * 8 + tig * 2;
            const float bv0 = __ldg(&bias[e]);
            const float bv1 = __ldg(&bias[e + 1]);
            float2 v0 = make_float2(c[mi][ni][0] + bv0, c[mi][ni][1] + bv1);
            float2 v1 = make_float2(c[mi][ni][2] + bv0, c[mi][ni][3] + bv1);
            if (MODE == 1) {
                const float2 x0 = *(const float2*)(Xres + rA * D_ + el);
                const float2 x1 = *(const float2*)(Xres + rB * D_ + el);
                v0.x += x0.x; v0.y += x0.y;
                v1.x += x1.x; v1.y += x1.y;
            }
            *(float2*)(dst + rA * D_ + el) = v0;
            *(float2*)(dst + rB * D_ + el) = v1;
        }
    }
}

// -------- reduction stage 1: per (batch, chunk) partial of fm(rope(K)) * V ---
__global__ __launch_bounds__(256)
void reduce_A_kernel()
{
    const int b     = blockIdx.x >> 7;
    const int chunk = blockIdx.x & (NCHUNK - 1);
    const int tid   = threadIdx.x;
    __shared__ float red[8];

    float acc[8];
    #pragma unroll
    for (int j = 0; j < 8; j++) acc[j] = 0.f;

    float invf[2];
    #pragma unroll
    for (int j = 0; j < 2; j++) {
        const int p = tid + 256 * j;
        invf[j] = exp2f((float)p * (float)NEG_L2T_OVER_512);
    }

    const int s0 = chunk * CHUNKS_S;
    for (int s = s0; s < s0 + CHUNKS_S; ++s) {
        const size_t rowoff = ((size_t)b * S_ + s) * D_;
        float kr[8];
        float sq = 0.f;
        #pragma unroll
        for (int j = 0; j < 4; ++j) {
            const int p = tid + 256 * j;
            const float2 kv = *(const float2*)(g_K + rowoff + 2 * p);
            float x0 = kv.x, x1 = kv.y;
            if (j < 2) {
                float sn, cs;
                sincosf((float)s * invf[j], &sn, &cs);
                const float r0 = x0 * cs - x1 * sn;
                const float r1 = x1 * cs + x0 * sn;
                x0 = r0; x1 = r1;
            }
            kr[2 * j] = x0; kr[2 * j + 1] = x1;
            sq = fmaf(x0, x0, fmaf(x1, x1, sq));
        }
        #pragma unroll
        for (int o = 16; o; o >>= 1) sq += __shfl_xor_sync(0xffffffffu, sq, o);
        if ((tid & 31) == 0) red[tid >> 5] = sq;
        __syncthreads();
        const float tot = red[0] + red[1] + red[2] + red[3]
                        + red[4] + red[5] + red[6] + red[7];
        __syncthreads();
        const float inv_n = 1.f / fmaxf(sqrtf(tot), 1e-12f);

        #pragma unroll
        for (int j = 0; j < 4; ++j) {
            const int p = tid + 256 * j;
            const float2 vv = *(const float2*)(g_V + rowoff + 2 * p);
            acc[2 * j]     = fmaf(kr[2 * j]     * inv_n, vv.x, acc[2 * j]);
            acc[2 * j + 1] = fmaf(kr[2 * j + 1] * inv_n, vv.y, acc[2 * j + 1]);
        }
    }
    float* dstp = g_Apart + ((size_t)b * NCHUNK + chunk) * D_;
    #pragma unroll
    for (int j = 0; j < 4; ++j) {
        const int p = tid + 256 * j;
        *(float2*)(dstp + 2 * p) = make_float2(acc[2 * j], acc[2 * j + 1]);
    }
}

// -------- reduction stage 2: fixed-order finalize ----------------------------
__global__ void finalize_A_kernel()
{
    const int i = blockIdx.x * 256 + threadIdx.x;
    const int b = i >> 11;
    const int d = i & (D_ - 1);
    float s = 0.f;
    for (int c = 0; c < NCHUNK; ++c)
        s += g_Apart[((size_t)b * NCHUNK + c) * D_ + d];
    g_A[i] = s;
}

// -------- Yb = fp16(A * rope(Q)), stored pair-PERMUTED for GEMM2 --------------
__global__ __launch_bounds__(256)
void yb_kernel()
{
    const int m = blockIdx.x;
    const int b = m >> 12;
    const int s = m & (S_ - 1);
    const int tid = threadIdx.x;
    const size_t rowoff = (size_t)m * D_;
    const float* Arow = g_A + b * D_;

    #pragma unroll
    for (int j = 0; j < 4; ++j) {
        const int p = tid + 256 * j;          // column pair index (0..1023)
        const float2 q = *(const float2*)(g_Q + rowoff + 2 * p);
        float x0 = q.x, x1 = q.y;
        if (j < 2) {
            const float invf = exp2f((float)p * (float)NEG_L2T_OVER_512);
            float sn, cs;
            sincosf((float)s * invf, &sn, &cs);
            const float r0 = x0 * cs - x1 * sn;
            const float r1 = x1 * cs + x0 * sn;
            x0 = r0; x1 = r1;
        }
        const float2 a = *(const float2*)(Arow + 2 * p);
        // permuted fp16 store: group G = p>>4, pg = p&15, kg = pg>>3, pp = pg&7
        // slot = (pp&3)*4 + (pp>>2) + 2*kg; half offset = G*32 + slot*2
        const int G  = p >> 4;
        const int pg = p & 15;
        const int slot = ((pg & 3) << 2) + ((pg >> 2) & 1) + ((pg >> 3) << 1);
        const unsigned hv = pack_h2(a.x * x0, a.y * x1);
        *(unsigned*)(&g_Yh[rowoff + G * 32 + slot * 2]) = hv;
    }
}

// ---------------- launch ------------------------------------------------------
extern "C" void kernel_launch(void* const* d_in, const int* in_sizes, int n_in,
                              void* d_out, int out_size)
{
    const float* X     = (const float*)d_in[0];   // [8,4096,2048]
    const float* W_in  = (const float*)d_in[1];   // [6144,2048]
    const float* b_in  = (const float*)d_in[2];   // [6144]
    const float* W_out = (const float*)d_in[3];   // [2048,2048]
    const float* b_out = (const float*)d_in[4];   // [2048]
    float* out = (float*)d_out;

    __half* xh; __half* w1h; __half* w2h;
    cudaGetSymbolAddress((void**)&xh,  g_Xh);
    cudaGetSymbolAddress((void**)&w1h, g_W1h);
    cudaGetSymbolAddress((void**)&w2h, g_W2h);

    cudaFuncSetAttribute(gemm_f16<0>, cudaFuncAttributeMaxDynamicSharedMemorySize, GEMM_SMEM);
    cudaFuncSetAttribute(gemm_f16<1>, cudaFuncAttributeMaxDynamicSharedMemorySize, GEMM_SMEM);

    // 0) fp32 -> permuted fp16 operands
    half_perm_kernel<<<(M_ * (D_/8)) / 256, 256>>>(X, xh, M_ * (D_/8));
    half_perm_kernel<<<(E1_ * (D_/8)) / 256, 256>>>(W_in, w1h, E1_ * (D_/8));
    half_perm_kernel<<<(D_ * (D_/8)) / 256, 256>>>(W_out, w2h, D_ * (D_/8));

    // 1) QKV = X @ W_in^T + b_in  ->  g_Q, g_K, g_V
    gemm_f16<0><<<dim3(E1_ / BN, M_ / BM), 256, GEMM_SMEM>>>(w1h, b_in, nullptr, nullptr);

    // 2) A = sum_s fm(rope(K)) * V
    reduce_A_kernel<<<B_ * NCHUNK, 256>>>();
    finalize_A_kernel<<<(B_ * D_) / 256, 256>>>();

    // 3) Yb = fp16(A ⊙ rope(Q))  (pair-permuted)
    yb_kernel<<<M_, 256>>>();

    // 4) out = Yb @ W_out^T + b_out + X
    gemm_f16<1><<<dim3(D_ / BN, M_ / BM), 256, GEMM_SMEM>>>(w2h, b_out, X, out);

    (void)in_sizes; (void)n_in; (void)out_size;
}